// round 10
// baseline (speedup 1.0000x reference)
#include <cuda_runtime.h>
#include <cuda_bf16.h>

// RAM multi-step transformer — LSU-optimized:
//  * lane-replicated bit arrays in smem -> conflict-free gather LDS
//  * conn_state held in registers (packed u16) across all 4 iterations
//  * L2::64B fetch granularity on table loads (halves DRAM bytes, confirmed)
//  * evict_last on in/out tables, fractional on state (cross-replay warm L2)
//
// x: (256,1024) i32 | conn_in: (2048,16) | conn_state: (1024,16) | conn_out: (512,16)
// mem_in: (2048,65536) f32 | mem_state: (1024,65536) f32 | mem_out: (512,65536) f32
// out: (256,512) f32

#define BATCH 256
#define IN_BITS 1024
#define N_IN 2048
#define N_ST 1024
#define N_OUT 512
#define TBL 65536
#define MAX_ITERS 4
#define THREADS 256

__device__ __forceinline__ unsigned long long mk_policy_pin() {
    unsigned long long pol;
    asm("createpolicy.fractional.L2::evict_last.b64 %0, 1.0;" : "=l"(pol));
    return pol;
}
__device__ __forceinline__ unsigned long long mk_policy_state() {
    unsigned long long pol;
    asm("createpolicy.fractional.L2::evict_last.L2::evict_first.b64 %0, 0.25;" : "=l"(pol));
    return pol;
}
__device__ __forceinline__ float ld_tbl64(const float* p, unsigned long long pol) {
    float v;
    asm("ld.global.nc.L2::cache_hint.L2::64B.f32 %0, [%1], %2;"
        : "=f"(v) : "l"(p), "l"(pol));
    return v;
}

// One bit from a lane-replicated bit array: word (idx>>5) copy for this lane
// lives at rep[(idx & ~31) + lane] — bank == lane, conflict-free.
__device__ __forceinline__ unsigned bitr(const unsigned* __restrict__ rep,
                                         int lane, int idx) {
    unsigned w = rep[(idx & ~31) + lane];
    return (w >> (idx & 31)) & 1u;
}

// Gather 16 bits given four int4 connection vectors.
__device__ __forceinline__ unsigned gather16r(const unsigned* __restrict__ rep, int lane,
                                              int4 c0, int4 c1, int4 c2, int4 c3) {
    unsigned a = 0;
    a |= bitr(rep, lane, c0.x) << 0;  a |= bitr(rep, lane, c0.y) << 1;
    a |= bitr(rep, lane, c0.z) << 2;  a |= bitr(rep, lane, c0.w) << 3;
    a |= bitr(rep, lane, c1.x) << 4;  a |= bitr(rep, lane, c1.y) << 5;
    a |= bitr(rep, lane, c1.z) << 6;  a |= bitr(rep, lane, c1.w) << 7;
    a |= bitr(rep, lane, c2.x) << 8;  a |= bitr(rep, lane, c2.y) << 9;
    a |= bitr(rep, lane, c2.z) << 10; a |= bitr(rep, lane, c2.w) << 11;
    a |= bitr(rep, lane, c3.x) << 12; a |= bitr(rep, lane, c3.y) << 13;
    a |= bitr(rep, lane, c3.z) << 14; a |= bitr(rep, lane, c3.w) << 15;
    return a;
}

// Gather 16 bits from 8 packed u16-pair connection words.
__device__ __forceinline__ unsigned gather16p(const unsigned* __restrict__ rep, int lane,
                                              const unsigned* __restrict__ cs) {
    unsigned a = 0;
    #pragma unroll
    for (int j = 0; j < 8; j++) {
        int lo = cs[j] & 0xFFFF;
        int hi = cs[j] >> 16;
        a |= bitr(rep, lane, lo) << (2 * j);
        a |= bitr(rep, lane, hi) << (2 * j + 1);
    }
    return a;
}

__global__ __launch_bounds__(THREADS, 2)
void ram_multistep_kernel(
    const int* __restrict__ x,
    const int4* __restrict__ conn_in,
    const int4* __restrict__ conn_state,
    const int4* __restrict__ conn_out,
    const float* __restrict__ mem_in,
    const float* __restrict__ mem_state,
    const float* __restrict__ mem_out,
    float* __restrict__ out)
{
    __shared__ unsigned repx[32 * 32];   // x bits, lane-replicated (4KB)
    __shared__ unsigned repA[96 * 32];   // [0,64): in-bits, [64,96): state (12KB)
    __shared__ unsigned repB[96 * 32];   // double buffer (12KB)

    const int b = blockIdx.x;
    const int tid = threadIdx.x;
    const int lane = tid & 31;
    const int warp = tid >> 5;           // 0..7

    const unsigned long long pol_pin   = mk_policy_pin();
    const unsigned long long pol_state = mk_policy_state();

    // ---- Pack + replicate x bits; zero state words of repA ----
    #pragma unroll
    for (int r = 0; r < 4; r++) {
        int bit = __ldg(x + b * IN_BITS + r * 256 + tid);
        unsigned w = __ballot_sync(0xFFFFFFFFu, bit != 0);
        repx[(r * 8 + warp) * 32 + lane] = w;       // own-lane copy, conflict-free
    }
    #pragma unroll
    for (int k = 0; k < 4; k++)
        repA[(64 + k * 8 + warp) * 32 + lane] = 0u; // initial state = 0
    __syncthreads();

    // ---- Input layer: 2048 neurons, 8 per thread ----
    {
        unsigned addr[8];
        #pragma unroll
        for (int r = 0; r < 8; r++) {
            const int4* c = conn_in + (r * 256 + tid) * 4;
            int4 c0 = __ldg(c + 0), c1 = __ldg(c + 1), c2 = __ldg(c + 2), c3 = __ldg(c + 3);
            addr[r] = gather16r(repx, lane, c0, c1, c2, c3);
        }
        float v[8];
        #pragma unroll
        for (int r = 0; r < 8; r++)
            v[r] = ld_tbl64(mem_in + (size_t)(r * 256 + tid) * TBL + addr[r], pol_pin);
        #pragma unroll
        for (int r = 0; r < 8; r++) {
            unsigned w = __ballot_sync(0xFFFFFFFFu, v[r] > 0.5f);
            repA[(r * 8 + warp) * 32 + lane] = w;   // every lane stores its copy
            repB[(r * 8 + warp) * 32 + lane] = w;
        }
    }

    // ---- Hoist conn_state into registers as packed u16 pairs (reused x4) ----
    unsigned cs[4][8];
    #pragma unroll
    for (int k = 0; k < 4; k++) {
        const int4* c = conn_state + (k * 256 + tid) * 4;
        int4 c0 = __ldg(c + 0), c1 = __ldg(c + 1), c2 = __ldg(c + 2), c3 = __ldg(c + 3);
        cs[k][0] = (unsigned)(c0.x & 0xFFFF) | ((unsigned)c0.y << 16);
        cs[k][1] = (unsigned)(c0.z & 0xFFFF) | ((unsigned)c0.w << 16);
        cs[k][2] = (unsigned)(c1.x & 0xFFFF) | ((unsigned)c1.y << 16);
        cs[k][3] = (unsigned)(c1.z & 0xFFFF) | ((unsigned)c1.w << 16);
        cs[k][4] = (unsigned)(c2.x & 0xFFFF) | ((unsigned)c2.y << 16);
        cs[k][5] = (unsigned)(c2.z & 0xFFFF) | ((unsigned)c2.w << 16);
        cs[k][6] = (unsigned)(c3.x & 0xFFFF) | ((unsigned)c3.y << 16);
        cs[k][7] = (unsigned)(c3.z & 0xFFFF) | ((unsigned)c3.w << 16);
    }
    __syncthreads();

    // ---- Recurrent state iterations: 4 per thread, 1 barrier/iter ----
    unsigned* cur = repA;
    unsigned* nxt = repB;
    for (int it = 0; it < MAX_ITERS; it++) {
        unsigned addr[4];
        #pragma unroll
        for (int k = 0; k < 4; k++)
            addr[k] = gather16p(cur, lane, cs[k]);
        float v[4];
        #pragma unroll
        for (int k = 0; k < 4; k++)
            v[k] = ld_tbl64(mem_state + (size_t)(k * 256 + tid) * TBL + addr[k], pol_state);
        #pragma unroll
        for (int k = 0; k < 4; k++) {
            unsigned w = __ballot_sync(0xFFFFFFFFu, v[k] > 0.5f);
            nxt[(64 + k * 8 + warp) * 32 + lane] = w;  // disjoint from cur
        }
        __syncthreads();
        unsigned* t = cur; cur = nxt; nxt = t;
    }

    // ---- Output layer: 512 neurons, 2 per thread (final state only) ----
    {
        unsigned addr[2];
        #pragma unroll
        for (int r = 0; r < 2; r++) {
            const int4* c = conn_out + (r * 256 + tid) * 4;
            int4 c0 = __ldg(c + 0), c1 = __ldg(c + 1), c2 = __ldg(c + 2), c3 = __ldg(c + 3);
            addr[r] = gather16r(cur, lane, c0, c1, c2, c3);
        }
        #pragma unroll
        for (int r = 0; r < 2; r++) {
            int n = r * 256 + tid;
            out[b * N_OUT + n] = ld_tbl64(mem_out + (size_t)n * TBL + addr[r], pol_pin);
        }
    }
}

extern "C" void kernel_launch(void* const* d_in, const int* in_sizes, int n_in,
                              void* d_out, int out_size) {
    const int* x            = (const int*)d_in[0];
    const int4* conn_in     = (const int4*)d_in[1];
    const int4* conn_state  = (const int4*)d_in[2];
    const int4* conn_out    = (const int4*)d_in[3];
    const float* mem_in     = (const float*)d_in[4];
    const float* mem_state  = (const float*)d_in[5];
    const float* mem_out    = (const float*)d_in[6];
    float* out = (float*)d_out;

    ram_multistep_kernel<<<BATCH, THREADS>>>(x, conn_in, conn_state, conn_out,
                                             mem_in, mem_state, mem_out, out);
}